// round 16
// baseline (speedup 1.0000x reference)
#include <cuda_runtime.h>
#include <cuda_bf16.h>
#include <cstdint>

#define N_NODES   100000
#define FDIM      64
#define MAX_E     1250000
#define SCAN_BLK  1024
#define MAX_SB    128
#define SROW      136   // bf16 elements per padded smem row (272 B)

typedef unsigned long long ull;

// ---------------- scratch (static __device__) ----------------
__device__ float4 g_xw4[(size_t)N_NODES * 16];   // layer-1 rows (dis-premult)
__device__ float4 g_h4 [(size_t)N_NODES * 16];   // layer-2 rows (dis-premult)
__device__ float  g_dis[N_NODES];
__device__ int    g_cnt[N_NODES];
__device__ int    g_rowstart[N_NODES + 1];
__device__ int    g_cursor[N_NODES];
__device__ int    g_csr[MAX_E];
__device__ int    g_flag[MAX_SB];
__device__ float4 g_wt4[2][64 * SROW * 2 / 16];  // pre-split Wt (bf16, smem layout)

__device__ __forceinline__ uint32_t smem_u32(const void* p) {
    uint32_t a;
    asm("{ .reg .u64 t; cvta.to.shared.u64 t, %1; cvt.u32.u64 %0, t; }"
        : "=r"(a) : "l"(p));
    return a;
}

__device__ __forceinline__ int probe_is64(const int* ei32, int* sflag) {
    if (threadIdx.x == 0) {
        int allz = 1;
        #pragma unroll
        for (int k = 0; k < 64; k++)
            if (ei32[2 * k + 1] != 0) { allz = 0; break; }
        *sflag = allz;
    }
    __syncthreads();
    return *sflag;
}

// ---------- W pre-split ----------
__global__ void k_wconv(const float* __restrict__ W1, const float* __restrict__ W2) {
    const float* W = (blockIdx.x == 0) ? W1 : W2;
    __nv_bfloat16* dst = (__nv_bfloat16*)g_wt4[blockIdx.x];
    for (int e = threadIdx.x; e < 64 * 64; e += 256) {
        int k  = e >> 6;
        int nn = e & 63;
        float w = W[e];
        __nv_bfloat16 hb = __float2bfloat16_rn(w);
        __nv_bfloat16 lb = __float2bfloat16_rn(w - __bfloat162float(hb));
        dst[nn * SROW + k]      = hb;
        dst[nn * SROW + 64 + k] = lb;
    }
}

// ---------------- histogram of dst ----------------
__global__ void k_hist(const int* __restrict__ ei32, int E, int n) {
    __shared__ int sis64;
    int is64 = probe_is64(ei32, &sis64);
    int e = blockIdx.x * blockDim.x + threadIdx.x;
    if (e < E) {
        int d;
        if (is64) d = (int)((const long long*)ei32)[(size_t)E + e];
        else      d = ei32[(size_t)E + e];
        d = d < 0 ? 0 : (d >= n ? n - 1 : d);
        atomicAdd(&g_cnt[d], 1);
    }
}

// ------ single-pass scan (decoupled lookback) ------
__global__ __launch_bounds__(256) void k_scan(int n, int E) {
    __shared__ int s[256];
    __shared__ int sbase;
    const int t   = threadIdx.x;
    const int bid = blockIdx.x;
    const int i0  = bid * SCAN_BLK + t * 4;

    int c[4];
    int sum = 0;
    #pragma unroll
    for (int k = 0; k < 4; k++) {
        int i = i0 + k;
        c[k] = (i < n) ? g_cnt[i] : 0;
        sum += c[k];
        if (i < n) g_dis[i] = rsqrtf((float)c[k] + 1.0f);
    }
    s[t] = sum;
    __syncthreads();
    for (int off = 1; off < 256; off <<= 1) {
        int a = (t >= off) ? s[t - off] : 0;
        __syncthreads();
        s[t] += a;
        __syncthreads();
    }
    int myIncl = s[t];
    int total  = s[255];
    if (t == 0) atomicExch(&g_flag[bid], total + 1);
    int part = 0;
    if (t < bid) {
        int v;
        do { v = atomicAdd(&g_flag[t], 0); } while (v == 0);
        part = v - 1;
    }
    __syncthreads();
    s[t] = part;
    __syncthreads();
    for (int off = 128; off > 0; off >>= 1) {
        if (t < off) s[t] += s[t + off];
        __syncthreads();
    }
    if (t == 0) {
        sbase = s[0];
        if (bid == 0) g_rowstart[n] = E;
    }
    __syncthreads();
    int base = sbase + myIncl - sum;
    #pragma unroll
    for (int k = 0; k < 4; k++) {
        int i = i0 + k;
        if (i < n) {
            g_rowstart[i] = base;
            g_cursor[i]   = base;
            base += c[k];
        }
    }
}

// -------- CSR fill + reset zero-invariants --------
__global__ void k_fill(const int* __restrict__ ei32, int E, int n) {
    __shared__ int sis64;
    int is64 = probe_is64(ei32, &sis64);
    int e = blockIdx.x * blockDim.x + threadIdx.x;
    if (e < E) {
        int s, d;
        if (is64) {
            const long long* ei64 = (const long long*)ei32;
            s = (int)ei64[e];
            d = (int)ei64[(size_t)E + e];
        } else {
            s = ei32[e];
            d = ei32[(size_t)E + e];
        }
        s = s < 0 ? 0 : (s >= n ? n - 1 : s);
        d = d < 0 ? 0 : (d >= n ? n - 1 : d);
        int pos = atomicAdd(&g_cursor[d], 1);
        g_csr[pos] = s;
        g_cnt[d]   = 0;
    }
    if (e < MAX_SB) g_flag[e] = 0;
}

// ======== shared GEMM pieces (B copy, mainloop, epilogue) ========
__device__ __forceinline__ void gemm_copy_B(char* sB, int widx, int tid) {
    const float4* src = g_wt4[widx];
    float4*       dst = (float4*)sB;
    #pragma unroll
    for (int i = 0; i < 4; i++) dst[tid + i * 256] = src[tid + i * 256];
    if (tid < 1088 - 1024) dst[tid + 1024] = src[tid + 1024];
}

// mainloop + epilogue: rows row0..row0+127 from sA, write dis-premult to dst
__device__ __forceinline__ void gemm_core(
    uint32_t sAu, uint32_t sBu, int row0, int n,
    float* __restrict__ dst, int lane, int wid)
{
    const int rowG = wid >> 1;
    const int colG = wid & 1;
    const int r0   = rowG * 32;
    const int c0   = colG * 32;

    uint32_t bRowIn = (uint32_t)((lane & 7) + ((lane >> 4) & 1) * 8);
    uint32_t bKof   = (uint32_t)(((lane >> 3) & 1) * 8);
    uint32_t bf[8][2][4];
    #pragma unroll
    for (int ch = 0; ch < 8; ch++)
        #pragma unroll
        for (int g16 = 0; g16 < 2; g16++) {
            uint32_t bAddr = sBu
                + (uint32_t)(c0 + g16 * 16 + bRowIn) * (SROW * 2)
                + (uint32_t)(ch * 16 + bKof) * 2;
            asm volatile("ldmatrix.sync.aligned.m8n8.x4.shared.b16 {%0,%1,%2,%3}, [%4];"
                         : "=r"(bf[ch][g16][0]), "=r"(bf[ch][g16][1]),
                           "=r"(bf[ch][g16][2]), "=r"(bf[ch][g16][3])
                         : "r"(bAddr));
        }

    float c[2][4][4];
    #pragma unroll
    for (int rt = 0; rt < 2; rt++)
        #pragma unroll
        for (int nt = 0; nt < 4; nt++)
            #pragma unroll
            for (int j = 0; j < 4; j++) c[rt][nt][j] = 0.f;

    uint32_t aLane = (uint32_t)(lane & 15);
    uint32_t aKof  = (uint32_t)((lane >> 4) * 8);

    #pragma unroll
    for (int kc = 0; kc < 8; kc++) {
        uint32_t a[2][4];
        #pragma unroll
        for (int rt = 0; rt < 2; rt++) {
            uint32_t aAddr = sAu
                + (uint32_t)(r0 + rt * 16 + aLane) * (SROW * 2)
                + (uint32_t)(kc * 16 + aKof) * 2;
            asm volatile("ldmatrix.sync.aligned.m8n8.x4.shared.b16 {%0,%1,%2,%3}, [%4];"
                         : "=r"(a[rt][0]), "=r"(a[rt][1]),
                           "=r"(a[rt][2]), "=r"(a[rt][3])
                         : "r"(aAddr));
        }
        const int nPair = (kc < 4) ? 2 : 1;
        #pragma unroll
        for (int bi = 0; bi < 2; bi++) {
            if (bi >= nPair) break;
            int bc = (kc < 4) ? (bi == 0 ? kc : kc + 4) : (kc - 4);
            #pragma unroll
            for (int rt = 0; rt < 2; rt++)
                #pragma unroll
                for (int g16 = 0; g16 < 2; g16++) {
                    asm volatile(
                        "mma.sync.aligned.m16n8k16.row.col.f32.bf16.bf16.f32 "
                        "{%0,%1,%2,%3}, {%4,%5,%6,%7}, {%8,%9}, {%0,%1,%2,%3};"
                        : "+f"(c[rt][g16*2][0]), "+f"(c[rt][g16*2][1]),
                          "+f"(c[rt][g16*2][2]), "+f"(c[rt][g16*2][3])
                        : "r"(a[rt][0]), "r"(a[rt][1]), "r"(a[rt][2]), "r"(a[rt][3]),
                          "r"(bf[bc][g16][0]), "r"(bf[bc][g16][1]));
                    asm volatile(
                        "mma.sync.aligned.m16n8k16.row.col.f32.bf16.bf16.f32 "
                        "{%0,%1,%2,%3}, {%4,%5,%6,%7}, {%8,%9}, {%0,%1,%2,%3};"
                        : "+f"(c[rt][g16*2+1][0]), "+f"(c[rt][g16*2+1][1]),
                          "+f"(c[rt][g16*2+1][2]), "+f"(c[rt][g16*2+1][3])
                        : "r"(a[rt][0]), "r"(a[rt][1]), "r"(a[rt][2]), "r"(a[rt][3]),
                          "r"(bf[bc][g16][2]), "r"(bf[bc][g16][3]));
                }
        }
    }

    int g  = lane >> 2;
    int t2 = (lane & 3) * 2;
    #pragma unroll
    for (int rt = 0; rt < 2; rt++) {
        int grLo = row0 + r0 + rt * 16 + g;
        int grHi = grLo + 8;
        float dLo = (grLo < n) ? g_dis[grLo] : 0.f;
        float dHi = (grHi < n) ? g_dis[grHi] : 0.f;
        #pragma unroll
        for (int nt = 0; nt < 4; nt++) {
            int col = c0 + nt * 8 + t2;
            if (grLo < n)
                *(float2*)&dst[(size_t)grLo * 64 + col] =
                    make_float2(dLo * c[rt][nt][0], dLo * c[rt][nt][1]);
            if (grHi < n)
                *(float2*)&dst[(size_t)grHi * 64 + col] =
                    make_float2(dHi * c[rt][nt][2], dHi * c[rt][nt][3]);
        }
    }
}

// -------- layer-1 GEMM: sA from x (fp32 global), split to bf16 -------------
__global__ __launch_bounds__(256) void k_gemm_mma(
    const float* __restrict__ in, int n)
{
    extern __shared__ char dsm[];
    char* sB = dsm;
    char* sA = dsm + 64 * (SROW * 2);

    const int tid  = threadIdx.x;
    const int lane = tid & 31;
    const int wid  = tid >> 5;
    const int row0 = blockIdx.x * 128;

    gemm_copy_B(sB, 0, tid);

    {
        int r  = tid >> 1;
        int h  = tid & 1;
        int gr = row0 + r;
        bool valid = gr < n;
        const float* xr = in + (size_t)gr * 64 + h * 32;
        char* rowp = sA + r * (SROW * 2);
        #pragma unroll
        for (int i = 0; i < 8; i++) {
            float4 f = valid ? *(const float4*)(xr + i * 4)
                             : make_float4(0.f, 0.f, 0.f, 0.f);
            __nv_bfloat162 h0 = __floats2bfloat162_rn(f.x, f.y);
            __nv_bfloat162 h1 = __floats2bfloat162_rn(f.z, f.w);
            float2 d0 = __bfloat1622float2(h0);
            float2 d1 = __bfloat1622float2(h1);
            __nv_bfloat162 l0 = __floats2bfloat162_rn(f.x - d0.x, f.y - d0.y);
            __nv_bfloat162 l1 = __floats2bfloat162_rn(f.z - d1.x, f.w - d1.y);
            int cc = h * 32 + i * 4;
            *(uint32_t*)(rowp + cc * 2)            = *(uint32_t*)&h0;
            *(uint32_t*)(rowp + (cc + 2) * 2)      = *(uint32_t*)&h1;
            *(uint32_t*)(rowp + (64 + cc) * 2)     = *(uint32_t*)&l0;
            *(uint32_t*)(rowp + (64 + cc + 2) * 2) = *(uint32_t*)&l1;
        }
    }
    __syncthreads();
    gemm_core(smem_u32(sA), smem_u32(sB), row0, n, (float*)g_xw4, lane, wid);
}

// ---- fused layer-2: gather h rows (CSR over g_xw4) -> relu -> bf16 sA -> GEMM
__global__ __launch_bounds__(256) void k_gg(
    const float* __restrict__ bias, int n)
{
    extern __shared__ char dsm[];
    char* sB = dsm;
    char* sA = dsm + 64 * (SROW * 2);

    const int tid  = threadIdx.x;
    const int lane = tid & 31;
    const int wid  = tid >> 5;
    const int row0 = blockIdx.x * 128;

    gemm_copy_B(sB, 1, tid);

    const float4* xw = g_xw4;
    const int half = lane >> 4;
    const int q    = lane & 15;
    float4 bb = make_float4(0.f, 0.f, 0.f, 0.f);
    if (half == 0) bb = ((const float4*)bias)[q];

    // gather phase: warp handles rows wid*16 .. wid*16+15
    for (int rr = 0; rr < 16; rr++) {
        int r  = wid * 16 + rr;
        int gr = row0 + r;
        char* rowp = sA + r * (SROW * 2);
        if (gr < n) {
            int   rs   = g_rowstart[gr];
            int   re   = g_rowstart[gr + 1];
            float disd = g_dis[gr];
            float4 acc = make_float4(0.f, 0.f, 0.f, 0.f);
            if (half == 0) acc = xw[(size_t)gr * 16 + q];
            int j = rs + half;
            for (; j + 6 < re; j += 8) {
                int s0 = g_csr[j];
                int s1 = g_csr[j + 2];
                int s2 = g_csr[j + 4];
                int s3 = g_csr[j + 6];
                float4 v0 = xw[(size_t)s0 * 16 + q];
                float4 v1 = xw[(size_t)s1 * 16 + q];
                float4 v2 = xw[(size_t)s2 * 16 + q];
                float4 v3 = xw[(size_t)s3 * 16 + q];
                acc.x += v0.x + v1.x; acc.y += v0.y + v1.y;
                acc.z += v0.z + v1.z; acc.w += v0.w + v1.w;
                acc.x += v2.x + v3.x; acc.y += v2.y + v3.y;
                acc.z += v2.z + v3.z; acc.w += v2.w + v3.w;
            }
            for (; j < re; j += 2) {
                float4 v = xw[(size_t)g_csr[j] * 16 + q];
                acc.x += v.x; acc.y += v.y; acc.z += v.z; acc.w += v.w;
            }
            acc.x += __shfl_xor_sync(0xffffffffu, acc.x, 16);
            acc.y += __shfl_xor_sync(0xffffffffu, acc.y, 16);
            acc.z += __shfl_xor_sync(0xffffffffu, acc.z, 16);
            acc.w += __shfl_xor_sync(0xffffffffu, acc.w, 16);
            if (half == 0) {
                float4 v = make_float4(fmaf(disd, acc.x, bb.x),
                                       fmaf(disd, acc.y, bb.y),
                                       fmaf(disd, acc.z, bb.z),
                                       fmaf(disd, acc.w, bb.w));
                v.x = fmaxf(v.x, 0.f); v.y = fmaxf(v.y, 0.f);
                v.z = fmaxf(v.z, 0.f); v.w = fmaxf(v.w, 0.f);
                __nv_bfloat162 h0 = __floats2bfloat162_rn(v.x, v.y);
                __nv_bfloat162 h1 = __floats2bfloat162_rn(v.z, v.w);
                float2 e0 = __bfloat1622float2(h0);
                float2 e1 = __bfloat1622float2(h1);
                __nv_bfloat162 l0 = __floats2bfloat162_rn(v.x - e0.x, v.y - e0.y);
                __nv_bfloat162 l1 = __floats2bfloat162_rn(v.z - e1.x, v.w - e1.y);
                *(uint32_t*)(rowp + q * 8)            = *(uint32_t*)&h0;
                *(uint32_t*)(rowp + q * 8 + 4)        = *(uint32_t*)&h1;
                *(uint32_t*)(rowp + 128 + q * 8)      = *(uint32_t*)&l0;
                *(uint32_t*)(rowp + 128 + q * 8 + 4)  = *(uint32_t*)&l1;
            }
        } else if (half == 0) {
            *(uint32_t*)(rowp + q * 8)           = 0u;
            *(uint32_t*)(rowp + q * 8 + 4)       = 0u;
            *(uint32_t*)(rowp + 128 + q * 8)     = 0u;
            *(uint32_t*)(rowp + 128 + q * 8 + 4) = 0u;
        }
    }
    __syncthreads();
    gemm_core(smem_u32(sA), smem_u32(sB), row0, n, (float*)g_h4, lane, wid);
}

// ------- final gather: out[d] = dis[d]*(row[d] + sum rows[s_j]) + b --------
__global__ __launch_bounds__(256) void k_gather(
    const float* __restrict__ bias, float* __restrict__ out_ext, int n)
{
    const float4* xw  = g_h4;             // layer-2 rows
    float4*       out = (float4*)out_ext;

    int warp = (blockIdx.x * blockDim.x + threadIdx.x) >> 5;
    if (warp >= n) return;
    int lane = threadIdx.x & 31;
    int half = lane >> 4;
    int q    = lane & 15;

    int   rs   = g_rowstart[warp];
    int   re   = g_rowstart[warp + 1];
    float disd = g_dis[warp];

    float4 acc = make_float4(0.f, 0.f, 0.f, 0.f);
    if (half == 0) acc = xw[(size_t)warp * 16 + q];

    int j = rs + half;
    for (; j + 6 < re; j += 8) {
        int s0 = g_csr[j];
        int s1 = g_csr[j + 2];
        int s2 = g_csr[j + 4];
        int s3 = g_csr[j + 6];
        float4 v0 = xw[(size_t)s0 * 16 + q];
        float4 v1 = xw[(size_t)s1 * 16 + q];
        float4 v2 = xw[(size_t)s2 * 16 + q];
        float4 v3 = xw[(size_t)s3 * 16 + q];
        acc.x += v0.x + v1.x; acc.y += v0.y + v1.y;
        acc.z += v0.z + v1.z; acc.w += v0.w + v1.w;
        acc.x += v2.x + v3.x; acc.y += v2.y + v3.y;
        acc.z += v2.z + v3.z; acc.w += v2.w + v3.w;
    }
    for (; j < re; j += 2) {
        float4 v = xw[(size_t)g_csr[j] * 16 + q];
        acc.x += v.x; acc.y += v.y; acc.z += v.z; acc.w += v.w;
    }
    acc.x += __shfl_xor_sync(0xffffffffu, acc.x, 16);
    acc.y += __shfl_xor_sync(0xffffffffu, acc.y, 16);
    acc.z += __shfl_xor_sync(0xffffffffu, acc.z, 16);
    acc.w += __shfl_xor_sync(0xffffffffu, acc.w, 16);

    if (half == 0) {
        float4 bb = ((const float4*)bias)[q];
        out[(size_t)warp * 16 + q] =
            make_float4(fmaf(disd, acc.x, bb.x), fmaf(disd, acc.y, bb.y),
                        fmaf(disd, acc.z, bb.z), fmaf(disd, acc.w, bb.w));
    }
}

// ---------------- launch ----------------
extern "C" void kernel_launch(void* const* d_in, const int* in_sizes, int n_in,
                              void* d_out, int out_size)
{
    int ix = -1, iei = -1, iw1 = -1, iw2 = -1, ib1 = -1, ib2 = -1;
    for (int i = 0; i < n_in; i++) {
        int s = in_sizes[i];
        if      (s == N_NODES * FDIM) { if (ix  < 0) ix  = i; }
        else if (s == 2 * MAX_E)      { if (iei < 0) iei = i; }
        else if (s == FDIM * FDIM)    { if (iw1 < 0) iw1 = i; else if (iw2 < 0) iw2 = i; }
        else if (s == FDIM)           { if (ib1 < 0) ib1 = i; else if (ib2 < 0) ib2 = i; }
    }
    if (ix < 0 || iei < 0 || iw1 < 0 || iw2 < 0 || ib1 < 0 || ib2 < 0) {
        ix = 0; iei = 1; iw1 = 2; ib1 = 3; iw2 = 4; ib2 = 5;
    }

    const float* x   = (const float*)d_in[ix];
    const int*   ei  = (const int*)d_in[iei];
    const float* W1  = (const float*)d_in[iw1];
    const float* b1  = (const float*)d_in[ib1];
    const float* W2  = (const float*)d_in[iw2];
    const float* b2  = (const float*)d_in[ib2];
    float*       out = (float*)d_out;

    int n = in_sizes[ix] / FDIM;
    int E = in_sizes[iei] / 2;
    if (n > N_NODES) n = N_NODES;
    if (E > MAX_E)   E = MAX_E;

    const int TB = 256;
    const int edgeBlocks = (E + TB - 1) / TB;
    const int nbScan     = (n + SCAN_BLK - 1) / SCAN_BLK;
    const int gthBlocks  = (n + 7) / 8;
    const int nTiles     = (n + 127) / 128;
    const int gemmSmem   = (64 + 128) * (SROW * 2);   // 52224 B

    static int attrSet = 0;
    static cudaStream_t s2;
    static cudaEvent_t evFork, evJoin;
    if (!attrSet) {
        cudaFuncSetAttribute(k_gemm_mma,
            cudaFuncAttributeMaxDynamicSharedMemorySize, gemmSmem);
        cudaFuncSetAttribute(k_gg,
            cudaFuncAttributeMaxDynamicSharedMemorySize, gemmSmem);
        cudaStreamCreateWithFlags(&s2, cudaStreamNonBlocking);
        cudaEventCreateWithFlags(&evFork, cudaEventDisableTiming);
        cudaEventCreateWithFlags(&evJoin, cudaEventDisableTiming);
        attrSet = 1;
    }

    k_wconv<<<2, 256>>>(W1, W2);
    k_hist<<<edgeBlocks, TB>>>(ei, E, n);
    k_scan<<<nbScan, 256>>>(n, E);

    // fork: CSR fill overlaps with layer-1 GEMM
    cudaEventRecord(evFork, 0);
    cudaStreamWaitEvent(s2, evFork, 0);
    k_fill<<<edgeBlocks, TB, 0, s2>>>(ei, E, n);
    cudaEventRecord(evJoin, s2);

    // layer-1 GEMM (rows = dis*(x@W1) into g_xw4)
    k_gemm_mma<<<nTiles, 256, gemmSmem>>>(x, n);

    // join, then fused gather+GEMM-2 (h = relu(gathered) @ W2 into g_h4)
    cudaStreamWaitEvent(0, evJoin, 0);
    k_gg<<<nTiles, 256, gemmSmem>>>(b1, n);

    // final gather from g_h4 into out
    k_gather<<<gthBlocks, TB>>>(b2, out, n);
}

// round 17
// speedup vs baseline: 1.1939x; 1.1939x over previous
#include <cuda_runtime.h>
#include <cuda_bf16.h>
#include <cstdint>

#define N_NODES   100000
#define FDIM      64
#define MAX_E     1250000
#define SCAN_BLK  1024
#define MAX_SB    128
#define SROW      136   // bf16 elements per padded smem row (272 B)

typedef unsigned long long ull;

// ---------------- scratch (static __device__) ----------------
__device__ float4 g_xw4[(size_t)N_NODES * 16];   // dis-premultiplied x@W rows
__device__ float4 g_h4 [(size_t)N_NODES * 16];   // layer-1 result
__device__ float  g_dis[N_NODES];
__device__ int    g_cnt[N_NODES];
__device__ int    g_rowstart[N_NODES + 1];
__device__ int    g_cursor[N_NODES];
__device__ int    g_csr[MAX_E];
__device__ int    g_flag[MAX_SB];
__device__ float4 g_wt4[2][64 * SROW * 2 / 16];  // pre-split Wt (bf16, smem layout)

__device__ __forceinline__ uint32_t smem_u32(const void* p) {
    uint32_t a;
    asm("{ .reg .u64 t; cvta.to.shared.u64 t, %1; cvt.u32.u64 %0, t; }"
        : "=r"(a) : "l"(p));
    return a;
}

__device__ __forceinline__ int probe_is64(const int* ei32, int* sflag) {
    if (threadIdx.x == 0) {
        int allz = 1;
        #pragma unroll
        for (int k = 0; k < 64; k++)
            if (ei32[2 * k + 1] != 0) { allz = 0; break; }
        *sflag = allz;
    }
    __syncthreads();
    return *sflag;
}

// ---------- W pre-split: Wt[nn][k] hi/lo bf16 in smem-ready layout ---------
__global__ void k_wconv(const float* __restrict__ W1, const float* __restrict__ W2) {
    const float* W = (blockIdx.x == 0) ? W1 : W2;
    __nv_bfloat16* dst = (__nv_bfloat16*)g_wt4[blockIdx.x];
    for (int e = threadIdx.x; e < 64 * 64; e += 256) {
        int k  = e >> 6;
        int nn = e & 63;
        float w = W[e];
        __nv_bfloat16 hb = __float2bfloat16_rn(w);
        __nv_bfloat16 lb = __float2bfloat16_rn(w - __bfloat162float(hb));
        dst[nn * SROW + k]      = hb;
        dst[nn * SROW + 64 + k] = lb;
    }
}

// ---------------- histogram of dst (4 edges/thread for MLP) ----------------
__global__ void k_hist(const int* __restrict__ ei32, int E, int n) {
    __shared__ int sis64;
    int is64 = probe_is64(ei32, &sis64);
    int base = blockIdx.x * (blockDim.x * 4) + threadIdx.x;
    int d[4];
    #pragma unroll
    for (int u = 0; u < 4; u++) {
        int e = base + u * 256;
        if (e < E) {
            int dd;
            if (is64) dd = (int)((const long long*)ei32)[(size_t)E + e];
            else      dd = ei32[(size_t)E + e];
            d[u] = dd < 0 ? 0 : (dd >= n ? n - 1 : dd);
        } else d[u] = -1;
    }
    #pragma unroll
    for (int u = 0; u < 4; u++)
        if (d[u] >= 0) atomicAdd(&g_cnt[d[u]], 1);
}

// ------ single-pass scan (decoupled lookback) ------
__global__ __launch_bounds__(256) void k_scan(int n, int E) {
    __shared__ int s[256];
    __shared__ int sbase;
    const int t   = threadIdx.x;
    const int bid = blockIdx.x;
    const int i0  = bid * SCAN_BLK + t * 4;

    int c[4];
    int sum = 0;
    #pragma unroll
    for (int k = 0; k < 4; k++) {
        int i = i0 + k;
        c[k] = (i < n) ? g_cnt[i] : 0;
        sum += c[k];
        if (i < n) g_dis[i] = rsqrtf((float)c[k] + 1.0f);
    }
    s[t] = sum;
    __syncthreads();
    for (int off = 1; off < 256; off <<= 1) {
        int a = (t >= off) ? s[t - off] : 0;
        __syncthreads();
        s[t] += a;
        __syncthreads();
    }
    int myIncl = s[t];
    int total  = s[255];
    if (t == 0) atomicExch(&g_flag[bid], total + 1);
    int part = 0;
    if (t < bid) {
        int v;
        do { v = atomicAdd(&g_flag[t], 0); } while (v == 0);
        part = v - 1;
    }
    __syncthreads();
    s[t] = part;
    __syncthreads();
    for (int off = 128; off > 0; off >>= 1) {
        if (t < off) s[t] += s[t + off];
        __syncthreads();
    }
    if (t == 0) {
        sbase = s[0];
        if (bid == 0) g_rowstart[n] = E;
    }
    __syncthreads();
    int base = sbase + myIncl - sum;
    #pragma unroll
    for (int k = 0; k < 4; k++) {
        int i = i0 + k;
        if (i < n) {
            g_rowstart[i] = base;
            g_cursor[i]   = base;
            base += c[k];
        }
    }
}

// -------- CSR fill (4 edges/thread) + reset zero-invariants ----------------
__global__ void k_fill(const int* __restrict__ ei32, int E, int n) {
    __shared__ int sis64;
    int is64 = probe_is64(ei32, &sis64);
    int base = blockIdx.x * (blockDim.x * 4) + threadIdx.x;
    int sv[4], dv[4];
    #pragma unroll
    for (int u = 0; u < 4; u++) {
        int e = base + u * 256;
        if (e < E) {
            int s, d;
            if (is64) {
                const long long* ei64 = (const long long*)ei32;
                s = (int)ei64[e];
                d = (int)ei64[(size_t)E + e];
            } else {
                s = ei32[e];
                d = ei32[(size_t)E + e];
            }
            sv[u] = s < 0 ? 0 : (s >= n ? n - 1 : s);
            dv[u] = d < 0 ? 0 : (d >= n ? n - 1 : d);
        } else dv[u] = -1;
    }
    int pos[4];
    #pragma unroll
    for (int u = 0; u < 4; u++)
        if (dv[u] >= 0) pos[u] = atomicAdd(&g_cursor[dv[u]], 1);
    #pragma unroll
    for (int u = 0; u < 4; u++)
        if (dv[u] >= 0) {
            g_csr[pos[u]] = sv[u];
            g_cnt[dv[u]]  = 0;       // restore zero-invariant
        }
    if (base < MAX_SB) g_flag[base] = 0;
}

// -------- GEMM via mma.sync bf16 split, persistent B fragments -------------
__global__ __launch_bounds__(256) void k_gemm_mma(
    const float* __restrict__ in_ext, int in_is_h,
    int widx, int relu, int n)
{
    extern __shared__ char dsm[];
    char* sB = dsm;                       // 64  * 272 = 17408 B
    char* sA = dsm + 64 * (SROW * 2);     // 128 * 272 = 34816 B

    const float* in = in_is_h ? (const float*)g_h4 : in_ext;
    float*       xw = (float*)g_xw4;

    const int tid  = threadIdx.x;
    const int lane = tid & 31;
    const int wid  = tid >> 5;
    const int row0 = blockIdx.x * 128;

    uint32_t sBu = smem_u32(sB);
    uint32_t sAu = smem_u32(sA);

    // ---- copy pre-split B (17408 B = 1088 float4) ----
    {
        const float4* src = g_wt4[widx];
        float4*       dst = (float4*)sB;
        #pragma unroll
        for (int i = 0; i < 4; i++) dst[tid + i * 256] = src[tid + i * 256];
        if (tid < 1088 - 1024) dst[tid + 1024] = src[tid + 1024];
    }

    // ---- fill A: row r = tid>>1, cols h*32..h*32+31 ----
    {
        int r  = tid >> 1;
        int h  = tid & 1;
        int gr = row0 + r;
        bool valid = gr < n;
        const float* xr = in + (size_t)gr * 64 + h * 32;
        char* rowp = sA + r * (SROW * 2);
        #pragma unroll
        for (int i = 0; i < 8; i++) {
            float4 f = valid ? *(const float4*)(xr + i * 4)
                             : make_float4(0.f, 0.f, 0.f, 0.f);
            if (relu) {
                f.x = fmaxf(f.x, 0.f); f.y = fmaxf(f.y, 0.f);
                f.z = fmaxf(f.z, 0.f); f.w = fmaxf(f.w, 0.f);
            }
            __nv_bfloat162 h0 = __floats2bfloat162_rn(f.x, f.y);
            __nv_bfloat162 h1 = __floats2bfloat162_rn(f.z, f.w);
            float2 d0 = __bfloat1622float2(h0);
            float2 d1 = __bfloat1622float2(h1);
            __nv_bfloat162 l0 = __floats2bfloat162_rn(f.x - d0.x, f.y - d0.y);
            __nv_bfloat162 l1 = __floats2bfloat162_rn(f.z - d1.x, f.w - d1.y);
            int c = h * 32 + i * 4;
            *(uint32_t*)(rowp + c * 2)              = *(uint32_t*)&h0;
            *(uint32_t*)(rowp + (c + 2) * 2)        = *(uint32_t*)&h1;
            *(uint32_t*)(rowp + (64 + c) * 2)       = *(uint32_t*)&l0;
            *(uint32_t*)(rowp + (64 + c + 2) * 2)   = *(uint32_t*)&l1;
        }
    }
    __syncthreads();

    const int rowG = wid >> 1;
    const int colG = wid & 1;
    const int r0   = rowG * 32;
    const int c0   = colG * 32;

    uint32_t bRowIn = (uint32_t)((lane & 7) + ((lane >> 4) & 1) * 8);
    uint32_t bKof   = (uint32_t)(((lane >> 3) & 1) * 8);
    uint32_t bf[8][2][4];
    #pragma unroll
    for (int ch = 0; ch < 8; ch++)
        #pragma unroll
        for (int g16 = 0; g16 < 2; g16++) {
            uint32_t bAddr = sBu
                + (uint32_t)(c0 + g16 * 16 + bRowIn) * (SROW * 2)
                + (uint32_t)(ch * 16 + bKof) * 2;
            asm volatile("ldmatrix.sync.aligned.m8n8.x4.shared.b16 {%0,%1,%2,%3}, [%4];"
                         : "=r"(bf[ch][g16][0]), "=r"(bf[ch][g16][1]),
                           "=r"(bf[ch][g16][2]), "=r"(bf[ch][g16][3])
                         : "r"(bAddr));
        }

    float c[2][4][4];
    #pragma unroll
    for (int rt = 0; rt < 2; rt++)
        #pragma unroll
        for (int nt = 0; nt < 4; nt++)
            #pragma unroll
            for (int j = 0; j < 4; j++) c[rt][nt][j] = 0.f;

    uint32_t aLane = (uint32_t)(lane & 15);
    uint32_t aKof  = (uint32_t)((lane >> 4) * 8);

    #pragma unroll
    for (int kc = 0; kc < 8; kc++) {
        uint32_t a[2][4];
        #pragma unroll
        for (int rt = 0; rt < 2; rt++) {
            uint32_t aAddr = sAu
                + (uint32_t)(r0 + rt * 16 + aLane) * (SROW * 2)
                + (uint32_t)(kc * 16 + aKof) * 2;
            asm volatile("ldmatrix.sync.aligned.m8n8.x4.shared.b16 {%0,%1,%2,%3}, [%4];"
                         : "=r"(a[rt][0]), "=r"(a[rt][1]),
                           "=r"(a[rt][2]), "=r"(a[rt][3])
                         : "r"(aAddr));
        }
        const int nPair = (kc < 4) ? 2 : 1;
        #pragma unroll
        for (int bi = 0; bi < 2; bi++) {
            if (bi >= nPair) break;
            int bc = (kc < 4) ? (bi == 0 ? kc : kc + 4) : (kc - 4);
            #pragma unroll
            for (int rt = 0; rt < 2; rt++)
                #pragma unroll
                for (int g16 = 0; g16 < 2; g16++) {
                    asm volatile(
                        "mma.sync.aligned.m16n8k16.row.col.f32.bf16.bf16.f32 "
                        "{%0,%1,%2,%3}, {%4,%5,%6,%7}, {%8,%9}, {%0,%1,%2,%3};"
                        : "+f"(c[rt][g16*2][0]), "+f"(c[rt][g16*2][1]),
                          "+f"(c[rt][g16*2][2]), "+f"(c[rt][g16*2][3])
                        : "r"(a[rt][0]), "r"(a[rt][1]), "r"(a[rt][2]), "r"(a[rt][3]),
                          "r"(bf[bc][g16][0]), "r"(bf[bc][g16][1]));
                    asm volatile(
                        "mma.sync.aligned.m16n8k16.row.col.f32.bf16.bf16.f32 "
                        "{%0,%1,%2,%3}, {%4,%5,%6,%7}, {%8,%9}, {%0,%1,%2,%3};"
                        : "+f"(c[rt][g16*2+1][0]), "+f"(c[rt][g16*2+1][1]),
                          "+f"(c[rt][g16*2+1][2]), "+f"(c[rt][g16*2+1][3])
                        : "r"(a[rt][0]), "r"(a[rt][1]), "r"(a[rt][2]), "r"(a[rt][3]),
                          "r"(bf[bc][g16][2]), "r"(bf[bc][g16][3]));
                }
        }
    }

    // ---- epilogue ----
    {
        int g  = lane >> 2;
        int t2 = (lane & 3) * 2;
        #pragma unroll
        for (int rt = 0; rt < 2; rt++) {
            int grLo = row0 + r0 + rt * 16 + g;
            int grHi = grLo + 8;
            float dLo = (grLo < n) ? g_dis[grLo] : 0.f;
            float dHi = (grHi < n) ? g_dis[grHi] : 0.f;
            #pragma unroll
            for (int nt = 0; nt < 4; nt++) {
                int col = c0 + nt * 8 + t2;
                if (grLo < n)
                    *(float2*)&xw[(size_t)grLo * 64 + col] =
                        make_float2(dLo * c[rt][nt][0], dLo * c[rt][nt][1]);
                if (grHi < n)
                    *(float2*)&xw[(size_t)grHi * 64 + col] =
                        make_float2(dHi * c[rt][nt][2], dHi * c[rt][nt][3]);
            }
        }
    }
}

// ------- CSR gather: out[d] = dis[d]*(row[d] + sum rows[s_j]) + b ----------
__global__ __launch_bounds__(256) void k_gather(
    const float* __restrict__ bias,
    float* __restrict__ out_ext, int out_is_h, int n)
{
    const float4* xw  = g_xw4;
    float4*       out = out_is_h ? g_h4 : (float4*)out_ext;

    int warp = (blockIdx.x * blockDim.x + threadIdx.x) >> 5;
    if (warp >= n) return;
    int lane = threadIdx.x & 31;
    int half = lane >> 4;
    int q    = lane & 15;

    int   rs   = g_rowstart[warp];
    int   re   = g_rowstart[warp + 1];
    float disd = g_dis[warp];

    float4 acc = make_float4(0.f, 0.f, 0.f, 0.f);
    if (half == 0) acc = xw[(size_t)warp * 16 + q];

    int j = rs + half;
    for (; j + 6 < re; j += 8) {
        int s0 = g_csr[j];
        int s1 = g_csr[j + 2];
        int s2 = g_csr[j + 4];
        int s3 = g_csr[j + 6];
        float4 v0 = xw[(size_t)s0 * 16 + q];
        float4 v1 = xw[(size_t)s1 * 16 + q];
        float4 v2 = xw[(size_t)s2 * 16 + q];
        float4 v3 = xw[(size_t)s3 * 16 + q];
        acc.x += v0.x + v1.x; acc.y += v0.y + v1.y;
        acc.z += v0.z + v1.z; acc.w += v0.w + v1.w;
        acc.x += v2.x + v3.x; acc.y += v2.y + v3.y;
        acc.z += v2.z + v3.z; acc.w += v2.w + v3.w;
    }
    for (; j < re; j += 2) {
        float4 v = xw[(size_t)g_csr[j] * 16 + q];
        acc.x += v.x; acc.y += v.y; acc.z += v.z; acc.w += v.w;
    }
    acc.x += __shfl_xor_sync(0xffffffffu, acc.x, 16);
    acc.y += __shfl_xor_sync(0xffffffffu, acc.y, 16);
    acc.z += __shfl_xor_sync(0xffffffffu, acc.z, 16);
    acc.w += __shfl_xor_sync(0xffffffffu, acc.w, 16);

    if (half == 0) {
        float4 bb = ((const float4*)bias)[q];
        out[(size_t)warp * 16 + q] =
            make_float4(fmaf(disd, acc.x, bb.x), fmaf(disd, acc.y, bb.y),
                        fmaf(disd, acc.z, bb.z), fmaf(disd, acc.w, bb.w));
    }
}

// ---------------- launch ----------------
extern "C" void kernel_launch(void* const* d_in, const int* in_sizes, int n_in,
                              void* d_out, int out_size)
{
    int ix = -1, iei = -1, iw1 = -1, iw2 = -1, ib1 = -1, ib2 = -1;
    for (int i = 0; i < n_in; i++) {
        int s = in_sizes[i];
        if      (s == N_NODES * FDIM) { if (ix  < 0) ix  = i; }
        else if (s == 2 * MAX_E)      { if (iei < 0) iei = i; }
        else if (s == FDIM * FDIM)    { if (iw1 < 0) iw1 = i; else if (iw2 < 0) iw2 = i; }
        else if (s == FDIM)           { if (ib1 < 0) ib1 = i; else if (ib2 < 0) ib2 = i; }
    }
    if (ix < 0 || iei < 0 || iw1 < 0 || iw2 < 0 || ib1 < 0 || ib2 < 0) {
        ix = 0; iei = 1; iw1 = 2; ib1 = 3; iw2 = 4; ib2 = 5;
    }

    const float* x   = (const float*)d_in[ix];
    const int*   ei  = (const int*)d_in[iei];
    const float* W1  = (const float*)d_in[iw1];
    const float* b1  = (const float*)d_in[ib1];
    const float* W2  = (const float*)d_in[iw2];
    const float* b2  = (const float*)d_in[ib2];
    float*       out = (float*)d_out;

    int n = in_sizes[ix] / FDIM;
    int E = in_sizes[iei] / 2;
    if (n > N_NODES) n = N_NODES;
    if (E > MAX_E)   E = MAX_E;

    const int TB = 256;
    const int edge4Blocks = (E + TB * 4 - 1) / (TB * 4);   // 4 edges/thread
    const int nbScan     = (n + SCAN_BLK - 1) / SCAN_BLK;
    const int gthBlocks  = (n + 7) / 8;
    const int nTiles     = (n + 127) / 128;
    const int gemmSmem   = (64 + 128) * (SROW * 2);   // 52224 B

    static int attrSet = 0;
    static cudaStream_t s2;
    static cudaEvent_t evFork, evW, evScan, evFill;
    if (!attrSet) {
        cudaFuncSetAttribute(k_gemm_mma,
            cudaFuncAttributeMaxDynamicSharedMemorySize, gemmSmem);
        cudaStreamCreateWithFlags(&s2, cudaStreamNonBlocking);
        cudaEventCreateWithFlags(&evFork, cudaEventDisableTiming);
        cudaEventCreateWithFlags(&evW,    cudaEventDisableTiming);
        cudaEventCreateWithFlags(&evScan, cudaEventDisableTiming);
        cudaEventCreateWithFlags(&evFill, cudaEventDisableTiming);
        attrSet = 1;
    }

    // side stream: wconv (overlaps hist), later fill (overlaps gemm1)
    cudaEventRecord(evFork, 0);
    cudaStreamWaitEvent(s2, evFork, 0);
    k_wconv<<<2, 256, 0, s2>>>(W1, W2);
    cudaEventRecord(evW, s2);

    // main stream: hist -> scan
    k_hist<<<edge4Blocks, TB>>>(ei, E, n);
    k_scan<<<nbScan, 256>>>(n, E);
    cudaEventRecord(evScan, 0);

    // fill on side stream (needs scan), overlaps layer-1 GEMM
    cudaStreamWaitEvent(s2, evScan, 0);
    k_fill<<<edge4Blocks, TB, 0, s2>>>(ei, E, n);
    cudaEventRecord(evFill, s2);

    // layer-1 GEMM (needs wconv)
    cudaStreamWaitEvent(0, evW, 0);
    k_gemm_mma<<<nTiles, 256, gemmSmem>>>(x, 0, 0, 0, n);

    // join: gather needs CSR
    cudaStreamWaitEvent(0, evFill, 0);
    k_gather<<<gthBlocks, TB>>>(b1, nullptr, 1, n);

    // layer 2
    k_gemm_mma<<<nTiles, 256, gemmSmem>>>(nullptr, 1, 1, 1, n);
    k_gather<<<gthBlocks, TB>>>(b2, out, 0, n);
}